// round 1
// baseline (speedup 1.0000x reference)
#include <cuda_runtime.h>
#include <math.h>

#define N_NODES 50000
#define N_EDGES 800000
#define C_IN    768
#define C1      256
#define C2      128
#define C3      2

// ---------------- scratch (device globals; no allocation allowed) ----------
__device__ float g_dinv[N_NODES];                 // deg -> rsqrt(deg)
__device__ float g_h1[(size_t)N_NODES * C1];      // x@W1
__device__ float g_a1[(size_t)N_NODES * C1];      // aggregated layer1
__device__ float g_h2[(size_t)N_NODES * C2];
__device__ float g_a2[(size_t)N_NODES * C2];
__device__ float g_h3[(size_t)N_NODES * C3];
__device__ float g_a3[(size_t)N_NODES * C3];

// ---------------- degree / norm -------------------------------------------
__global__ void k_deg_init() {
    int i = blockIdx.x * blockDim.x + threadIdx.x;
    if (i < N_NODES) g_dinv[i] = 1.0f;   // self loop contributes 1
}

__global__ void k_deg_acc(const int* __restrict__ dst) {
    int e = blockIdx.x * blockDim.x + threadIdx.x;
    if (e < N_EDGES) atomicAdd(&g_dinv[dst[e]], 1.0f);
}

__global__ void k_dinv() {
    int i = blockIdx.x * blockDim.x + threadIdx.x;
    if (i < N_NODES) g_dinv[i] = rsqrtf(g_dinv[i]);   // deg >= 1 always
}

// ---------------- SGEMM: C[M,N] = A[M,K] @ B[K,N] --------------------------
// 128x128 block tile, BK=8, 256 threads, 8x8 per thread.
// Requires: N % 128 == 0, K % 8 == 0. M guarded.
__global__ void sgemm_128x128(const float* __restrict__ A,
                              const float* __restrict__ B,
                              float* __restrict__ C,
                              int M, int K, int N) {
    __shared__ float As[8][128];
    __shared__ float Bs[8][128];
    const int tid = threadIdx.x;
    const int bm = blockIdx.y * 128;
    const int bn = blockIdx.x * 128;
    const int tx = tid % 16;          // col group
    const int ty = tid / 16;          // row group

    float acc[8][8];
#pragma unroll
    for (int i = 0; i < 8; i++)
#pragma unroll
        for (int j = 0; j < 8; j++) acc[i][j] = 0.0f;

    for (int k0 = 0; k0 < K; k0 += 8) {
        // A tile: 128 rows x 8 cols -> As[c][r] (transposed)
#pragma unroll
        for (int i = 0; i < 4; i++) {
            int idx = tid + i * 256;          // 0..1023
            int r = idx >> 3, c = idx & 7;
            int gr = bm + r;
            As[c][r] = (gr < M) ? A[(size_t)gr * K + k0 + c] : 0.0f;
        }
        // B tile: 8 rows x 128 cols
#pragma unroll
        for (int i = 0; i < 4; i++) {
            int idx = tid + i * 256;
            int r = idx >> 7, c = idx & 127;
            Bs[r][c] = B[(size_t)(k0 + r) * N + bn + c];
        }
        __syncthreads();

#pragma unroll
        for (int kk = 0; kk < 8; kk++) {
            float a[8], b[8];
#pragma unroll
            for (int i = 0; i < 8; i++) a[i] = As[kk][ty * 8 + i];
#pragma unroll
            for (int j = 0; j < 8; j++) b[j] = Bs[kk][tx * 8 + j];
#pragma unroll
            for (int i = 0; i < 8; i++)
#pragma unroll
                for (int j = 0; j < 8; j++) acc[i][j] += a[i] * b[j];
        }
        __syncthreads();
    }

#pragma unroll
    for (int i = 0; i < 8; i++) {
        int gr = bm + ty * 8 + i;
        if (gr < M) {
#pragma unroll
            for (int j = 0; j < 8; j++)
                C[(size_t)gr * N + bn + tx * 8 + j] = acc[i][j];
        }
    }
}

// ---------------- aggregation ----------------------------------------------
// init agg with the self-loop term: agg[i,:] = dinv[i]^2 * h[i,:]
template <int C>
__global__ void k_self_init(const float* __restrict__ h, float* __restrict__ agg) {
    size_t i = (size_t)blockIdx.x * blockDim.x + threadIdx.x;
    if (i < (size_t)N_NODES * C) {
        int node = (int)(i / C);
        float di = g_dinv[node];
        agg[i] = h[i] * di * di;
    }
}

// warp per edge: agg[dst,:] += dinv[src]*dinv[dst] * h[src,:]
template <int C>
__global__ void k_edge_scatter(const int* __restrict__ src,
                               const int* __restrict__ dst,
                               const float* __restrict__ h,
                               float* __restrict__ agg) {
    int warp = (blockIdx.x * blockDim.x + threadIdx.x) >> 5;
    int lane = threadIdx.x & 31;
    if (warp >= N_EDGES) return;
    int s = src[warp];
    int d = dst[warp];
    float w = g_dinv[s] * g_dinv[d];
    const float* hs = h + (size_t)s * C;
    float* ad = agg + (size_t)d * C;
#pragma unroll
    for (int c = lane; c < C; c += 32)
        atomicAdd(&ad[c], hs[c] * w);
}

// thread per edge for C=2 (final layer)
__global__ void k_edge_scatter2(const int* __restrict__ src,
                                const int* __restrict__ dst,
                                const float* __restrict__ h,
                                float* __restrict__ agg) {
    int e = blockIdx.x * blockDim.x + threadIdx.x;
    if (e >= N_EDGES) return;
    int s = src[e];
    int d = dst[e];
    float w = g_dinv[s] * g_dinv[d];
    atomicAdd(&agg[(size_t)d * 2 + 0], h[(size_t)s * 2 + 0] * w);
    atomicAdd(&agg[(size_t)d * 2 + 1], h[(size_t)s * 2 + 1] * w);
}

template <int C>
__global__ void k_bias_relu(float* __restrict__ a, const float* __restrict__ b) {
    size_t i = (size_t)blockIdx.x * blockDim.x + threadIdx.x;
    if (i < (size_t)N_NODES * C) {
        int c = (int)(i % C);
        a[i] = fmaxf(a[i] + b[c], 0.0f);
    }
}

// ---------------- layer-3 GEMM (K=128 -> 2 outputs), warp per row ----------
__global__ void k_gemm3(const float* __restrict__ A, const float* __restrict__ W,
                        float* __restrict__ out) {
    int warp = (blockIdx.x * blockDim.x + threadIdx.x) >> 5;
    int lane = threadIdx.x & 31;
    if (warp >= N_NODES) return;
    const float* ar = A + (size_t)warp * C2;
    float a0 = 0.0f, a1 = 0.0f;
#pragma unroll
    for (int k = lane; k < C2; k += 32) {
        float v = ar[k];
        a0 += v * W[k * 2 + 0];
        a1 += v * W[k * 2 + 1];
    }
#pragma unroll
    for (int o = 16; o > 0; o >>= 1) {
        a0 += __shfl_down_sync(0xffffffffu, a0, o);
        a1 += __shfl_down_sync(0xffffffffu, a1, o);
    }
    if (lane == 0) {
        out[(size_t)warp * 2 + 0] = a0;
        out[(size_t)warp * 2 + 1] = a1;
    }
}

__global__ void k_sigmoid_out(const float* __restrict__ a, const float* __restrict__ b,
                              float* __restrict__ out) {
    int i = blockIdx.x * blockDim.x + threadIdx.x;
    if (i < N_NODES * 2) {
        float v = a[i] + b[i & 1];
        out[i] = 1.0f / (1.0f + expf(-v));
    }
}

// ---------------- launch ----------------------------------------------------
extern "C" void kernel_launch(void* const* d_in, const int* in_sizes, int n_in,
                              void* d_out, int out_size) {
    const float* x  = (const float*)d_in[0];
    const int*   ei = (const int*)d_in[1];      // [2, N_EDGES] row-major
    const float* W1 = (const float*)d_in[2];
    const float* b1 = (const float*)d_in[3];
    const float* W2 = (const float*)d_in[4];
    const float* b2 = (const float*)d_in[5];
    const float* W3 = (const float*)d_in[6];
    const float* b3 = (const float*)d_in[7];
    float* out = (float*)d_out;

    const int* src = ei;
    const int* dst = ei + N_EDGES;

    float* dinv; cudaGetSymbolAddress((void**)&dinv, g_dinv);
    float* h1;   cudaGetSymbolAddress((void**)&h1, g_h1);
    float* a1;   cudaGetSymbolAddress((void**)&a1, g_a1);
    float* h2;   cudaGetSymbolAddress((void**)&h2, g_h2);
    float* a2;   cudaGetSymbolAddress((void**)&a2, g_a2);
    float* h3;   cudaGetSymbolAddress((void**)&h3, g_h3);
    float* a3;   cudaGetSymbolAddress((void**)&a3, g_a3);

    const int T = 256;

    // norm build
    k_deg_init<<<(N_NODES + T - 1) / T, T>>>();
    k_deg_acc<<<(N_EDGES + T - 1) / T, T>>>(dst);
    k_dinv<<<(N_NODES + T - 1) / T, T>>>();

    // ---- layer 1: h1 = x @ W1 ; a1 = A_norm h1 ; relu(a1 + b1)
    {
        dim3 grid(C1 / 128, (N_NODES + 127) / 128);
        sgemm_128x128<<<grid, 256>>>(x, W1, h1, N_NODES, C_IN, C1);
    }
    k_self_init<C1><<<((size_t)N_NODES * C1 + T - 1) / T, T>>>(h1, a1);
    k_edge_scatter<C1><<<(N_EDGES * 32 + T - 1) / T, T>>>(src, dst, h1, a1);
    k_bias_relu<C1><<<((size_t)N_NODES * C1 + T - 1) / T, T>>>(a1, b1);

    // ---- layer 2
    {
        dim3 grid(C2 / 128, (N_NODES + 127) / 128);
        sgemm_128x128<<<grid, 256>>>(a1, W2, h2, N_NODES, C1, C2);
    }
    k_self_init<C2><<<((size_t)N_NODES * C2 + T - 1) / T, T>>>(h2, a2);
    k_edge_scatter<C2><<<(N_EDGES * 32 + T - 1) / T, T>>>(src, dst, h2, a2);
    k_bias_relu<C2><<<((size_t)N_NODES * C2 + T - 1) / T, T>>>(a2, b2);

    // ---- layer 3: h3 = a2 @ W3 ; a3 = A_norm h3 ; sigmoid(a3 + b3)
    k_gemm3<<<(N_NODES * 32 + T - 1) / T, T>>>(a2, W3, h3);
    k_self_init<C3><<<(N_NODES * C3 + T - 1) / T, T>>>(h3, a3);
    k_edge_scatter2<<<(N_EDGES + T - 1) / T, T>>>(src, dst, h3, a3);
    k_sigmoid_out<<<(N_NODES * 2 + T - 1) / T, T>>>(a3, b3, out);
}

// round 3
// speedup vs baseline: 2.1438x; 2.1438x over previous
#include <cuda_runtime.h>
#include <math.h>

#define N_NODES 50000
#define N_EDGES 800000
#define C_IN    768
#define C1      256
#define C2      128
#define C3      2

// ---------------- scratch (device globals; no allocation allowed) ----------
__device__ float g_dinv[N_NODES];
__device__ float g_h1[(size_t)N_NODES * C1];
__device__ float g_a1[(size_t)N_NODES * C1];
__device__ float g_h2[(size_t)N_NODES * C2];
__device__ float g_a2[(size_t)N_NODES * C2];
__device__ float g_h3[(size_t)N_NODES * C3];
__device__ float g_a3[(size_t)N_NODES * C3];

// ---------------- degree / norm -------------------------------------------
__global__ void k_deg_init() {
    int i = blockIdx.x * blockDim.x + threadIdx.x;
    if (i < N_NODES) g_dinv[i] = 1.0f;   // self loop contributes 1
}

__global__ void k_deg_acc(const int* __restrict__ dst) {
    int e = blockIdx.x * blockDim.x + threadIdx.x;
    if (e < N_EDGES) atomicAdd(&g_dinv[dst[e]], 1.0f);
}

__global__ void k_dinv() {
    int i = blockIdx.x * blockDim.x + threadIdx.x;
    if (i < N_NODES) g_dinv[i] = rsqrtf(g_dinv[i]);
}

// ---------------- TF32 tensor-core GEMM ------------------------------------
// C[M,N] = A[M,K] @ B[K,N], fp32 in/out, TF32 mma with fp32 accumulate.
// BM=BN=128, BK=16, 256 threads = 8 warps, warp tile 64x32 (2x4 warp grid),
// each warp: 4x4 grid of m16n8k8 mma. Double-buffered smem, +8-word pad.
// Requires: N % 128 == 0, K % 16 == 0. M guarded.

__device__ __forceinline__ float tf32r(float x) {
    unsigned u;
    asm("cvt.rna.tf32.f32 %0, %1;" : "=r"(u) : "f"(x));
    return __uint_as_float(u);
}

#define GLD 136   // padded row stride (words)

__global__ void __launch_bounds__(256) tf32_gemm(const float* __restrict__ A,
                                                 const float* __restrict__ B,
                                                 float* __restrict__ C,
                                                 int M, int K, int N) {
    __shared__ float As[2][16][GLD];   // [k][m]
    __shared__ float Bs[2][16][GLD];   // [k][n]

    const int tid  = threadIdx.x;
    const int warp = tid >> 5;
    const int lane = tid & 31;
    const int gid  = lane >> 2;   // 0..7
    const int tig  = lane & 3;    // 0..3
    const int wm   = warp & 1;    // 2 m-warps
    const int wn   = warp >> 1;   // 4 n-warps
    const int bm   = blockIdx.y * 128;
    const int bn   = blockIdx.x * 128;

    const int ar = tid >> 1;
    const int ak = (tid & 1) * 8;

    float acc[4][4][4];
#pragma unroll
    for (int i = 0; i < 4; i++)
#pragma unroll
        for (int j = 0; j < 4; j++)
#pragma unroll
            for (int q = 0; q < 4; q++) acc[i][j][q] = 0.0f;

    float4 la0, la1, lb0, lb1;

    // ---- prologue: load tile 0 into buf 0
    {
        int gr = bm + ar;
        if (gr < M) {
            la0 = *(const float4*)(A + (size_t)gr * K + ak);
            la1 = *(const float4*)(A + (size_t)gr * K + ak + 4);
        } else {
            la0 = make_float4(0.f, 0.f, 0.f, 0.f); la1 = la0;
        }
#pragma unroll
        for (int i = 0; i < 2; i++) {
            int f = tid + i * 256;
            int r = f >> 5, c4 = f & 31;
            float4 v = *(const float4*)(B + (size_t)r * N + bn + c4 * 4);
            if (i == 0) lb0 = v; else lb1 = v;
        }
        As[0][ak + 0][ar] = tf32r(la0.x); As[0][ak + 1][ar] = tf32r(la0.y);
        As[0][ak + 2][ar] = tf32r(la0.z); As[0][ak + 3][ar] = tf32r(la0.w);
        As[0][ak + 4][ar] = tf32r(la1.x); As[0][ak + 5][ar] = tf32r(la1.y);
        As[0][ak + 6][ar] = tf32r(la1.z); As[0][ak + 7][ar] = tf32r(la1.w);
#pragma unroll
        for (int i = 0; i < 2; i++) {
            int f = tid + i * 256;
            int r = f >> 5, c4 = f & 31;
            float4 v = (i == 0) ? lb0 : lb1;
            Bs[0][r][c4 * 4 + 0] = tf32r(v.x);
            Bs[0][r][c4 * 4 + 1] = tf32r(v.y);
            Bs[0][r][c4 * 4 + 2] = tf32r(v.z);
            Bs[0][r][c4 * 4 + 3] = tf32r(v.w);
        }
    }
    __syncthreads();

    const int nIter = K / 16;
    for (int it = 0; it < nIter; it++) {
        int buf = it & 1;
        bool hasNext = (it + 1) < nIter;

        if (hasNext) {
            int k0 = (it + 1) * 16;
            int gr = bm + ar;
            if (gr < M) {
                la0 = *(const float4*)(A + (size_t)gr * K + k0 + ak);
                la1 = *(const float4*)(A + (size_t)gr * K + k0 + ak + 4);
            } else {
                la0 = make_float4(0.f, 0.f, 0.f, 0.f); la1 = la0;
            }
            {
                int f = tid;
                int r = f >> 5, c4 = f & 31;
                lb0 = *(const float4*)(B + (size_t)(k0 + r) * N + bn + c4 * 4);
                f = tid + 256; r = f >> 5; c4 = f & 31;
                lb1 = *(const float4*)(B + (size_t)(k0 + r) * N + bn + c4 * 4);
            }
        }

#pragma unroll
        for (int ks = 0; ks < 2; ks++) {
            int kk = ks * 8;
            unsigned af[4][4], bf[4][2];
#pragma unroll
            for (int im = 0; im < 4; im++) {
                int m = wm * 64 + im * 16 + gid;
                af[im][0] = __float_as_uint(As[buf][kk + tig][m]);
                af[im][1] = __float_as_uint(As[buf][kk + tig][m + 8]);
                af[im][2] = __float_as_uint(As[buf][kk + tig + 4][m]);
                af[im][3] = __float_as_uint(As[buf][kk + tig + 4][m + 8]);
            }
#pragma unroll
            for (int in_ = 0; in_ < 4; in_++) {
                int n = wn * 32 + in_ * 8 + gid;
                bf[in_][0] = __float_as_uint(Bs[buf][kk + tig][n]);
                bf[in_][1] = __float_as_uint(Bs[buf][kk + tig + 4][n]);
            }
#pragma unroll
            for (int im = 0; im < 4; im++)
#pragma unroll
                for (int in_ = 0; in_ < 4; in_++) {
                    asm volatile(
                        "mma.sync.aligned.m16n8k8.row.col.f32.tf32.tf32.f32 "
                        "{%0,%1,%2,%3}, {%4,%5,%6,%7}, {%8,%9}, {%0,%1,%2,%3};"
                        : "+f"(acc[im][in_][0]), "+f"(acc[im][in_][1]),
                          "+f"(acc[im][in_][2]), "+f"(acc[im][in_][3])
                        : "r"(af[im][0]), "r"(af[im][1]),
                          "r"(af[im][2]), "r"(af[im][3]),
                          "r"(bf[in_][0]), "r"(bf[in_][1]));
                }
        }

        if (hasNext) {
            int nb = buf ^ 1;
            As[nb][ak + 0][ar] = tf32r(la0.x); As[nb][ak + 1][ar] = tf32r(la0.y);
            As[nb][ak + 2][ar] = tf32r(la0.z); As[nb][ak + 3][ar] = tf32r(la0.w);
            As[nb][ak + 4][ar] = tf32r(la1.x); As[nb][ak + 5][ar] = tf32r(la1.y);
            As[nb][ak + 6][ar] = tf32r(la1.z); As[nb][ak + 7][ar] = tf32r(la1.w);
            {
                int f = tid;
                int r = f >> 5, c4 = f & 31;
                Bs[nb][r][c4 * 4 + 0] = tf32r(lb0.x);
                Bs[nb][r][c4 * 4 + 1] = tf32r(lb0.y);
                Bs[nb][r][c4 * 4 + 2] = tf32r(lb0.z);
                Bs[nb][r][c4 * 4 + 3] = tf32r(lb0.w);
                f = tid + 256; r = f >> 5; c4 = f & 31;
                Bs[nb][r][c4 * 4 + 0] = tf32r(lb1.x);
                Bs[nb][r][c4 * 4 + 1] = tf32r(lb1.y);
                Bs[nb][r][c4 * 4 + 2] = tf32r(lb1.z);
                Bs[nb][r][c4 * 4 + 3] = tf32r(lb1.w);
            }
            __syncthreads();
        }
    }

    // ---- epilogue
#pragma unroll
    for (int im = 0; im < 4; im++) {
        int r0 = bm + wm * 64 + im * 16 + gid;
        int r1 = r0 + 8;
#pragma unroll
        for (int in_ = 0; in_ < 4; in_++) {
            int c = bn + wn * 32 + in_ * 8 + 2 * tig;
            if (r0 < M) {
                float2 v = make_float2(acc[im][in_][0], acc[im][in_][1]);
                *(float2*)(C + (size_t)r0 * N + c) = v;
            }
            if (r1 < M) {
                float2 v = make_float2(acc[im][in_][2], acc[im][in_][3]);
                *(float2*)(C + (size_t)r1 * N + c) = v;
            }
        }
    }
}

// ---------------- aggregation ----------------------------------------------
__device__ __forceinline__ void red_add_v4(float* p, float a, float b, float c, float d) {
    asm volatile("red.global.add.v4.f32 [%0], {%1,%2,%3,%4};"
                 :: "l"(p), "f"(a), "f"(b), "f"(c), "f"(d) : "memory");
}

// agg[i,:] = dinv[i]^2 * h[i,:]   (vectorized float4; requires C % 4 == 0)
template <int C>
__global__ void k_self_init(const float* __restrict__ h, float* __restrict__ agg) {
    static_assert(C % 4 == 0, "C must be a multiple of 4");
    size_t i = (size_t)blockIdx.x * blockDim.x + threadIdx.x;
    const size_t total = (size_t)N_NODES * (C / 4);
    if (i < total) {
        int node = (int)(i / (C / 4));
        float di = g_dinv[node];
        float s = di * di;
        float4 v = ((const float4*)h)[i];
        v.x *= s; v.y *= s; v.z *= s; v.w *= s;
        ((float4*)agg)[i] = v;
    }
}

// layer-3 (C=2) self init: one thread per node, float2. MUST fully rewrite a3
// every call (graph replays would otherwise accumulate onto stale state).
__global__ void k_self_init2(const float* __restrict__ h, float* __restrict__ agg) {
    int i = blockIdx.x * blockDim.x + threadIdx.x;
    if (i < N_NODES) {
        float di = g_dinv[i];
        float s = di * di;
        float2 v = ((const float2*)h)[i];
        v.x *= s; v.y *= s;
        ((float2*)agg)[i] = v;
    }
}

// warp per edge: agg[dst,:] += dinv[src]*dinv[dst] * h[src,:]  (float4 + red.v4)
template <int C>
__global__ void k_edge_scatter(const int* __restrict__ src,
                               const int* __restrict__ dst,
                               const float* __restrict__ h,
                               float* __restrict__ agg) {
    int warp = (blockIdx.x * blockDim.x + threadIdx.x) >> 5;
    int lane = threadIdx.x & 31;
    if (warp >= N_EDGES) return;
    int s = src[warp];
    int d = dst[warp];
    float w = g_dinv[s] * g_dinv[d];
    const float4* hs = (const float4*)(h + (size_t)s * C);
    float* ad = agg + (size_t)d * C;
#pragma unroll
    for (int c = lane; c < C / 4; c += 32) {
        float4 v = hs[c];
        red_add_v4(ad + c * 4, v.x * w, v.y * w, v.z * w, v.w * w);
    }
}

// thread per edge for C=2 (final layer)
__global__ void k_edge_scatter2(const int* __restrict__ src,
                                const int* __restrict__ dst,
                                const float* __restrict__ h,
                                float* __restrict__ agg) {
    int e = blockIdx.x * blockDim.x + threadIdx.x;
    if (e >= N_EDGES) return;
    int s = src[e];
    int d = dst[e];
    float w = g_dinv[s] * g_dinv[d];
    atomicAdd(&agg[(size_t)d * 2 + 0], h[(size_t)s * 2 + 0] * w);
    atomicAdd(&agg[(size_t)d * 2 + 1], h[(size_t)s * 2 + 1] * w);
}

template <int C>
__global__ void k_bias_relu(float* __restrict__ a, const float* __restrict__ b) {
    static_assert(C % 4 == 0, "C must be a multiple of 4");
    size_t i = (size_t)blockIdx.x * blockDim.x + threadIdx.x;
    const size_t total = (size_t)N_NODES * (C / 4);
    if (i < total) {
        int c4 = (int)(i % (C / 4));
        float4 bb = ((const float4*)b)[c4];
        float4 v = ((float4*)a)[i];
        v.x = fmaxf(v.x + bb.x, 0.0f);
        v.y = fmaxf(v.y + bb.y, 0.0f);
        v.z = fmaxf(v.z + bb.z, 0.0f);
        v.w = fmaxf(v.w + bb.w, 0.0f);
        ((float4*)a)[i] = v;
    }
}

// ---------------- layer-3 GEMM (K=128 -> 2 outputs), warp per row ----------
__global__ void k_gemm3(const float* __restrict__ A, const float* __restrict__ W,
                        float* __restrict__ out) {
    int warp = (blockIdx.x * blockDim.x + threadIdx.x) >> 5;
    int lane = threadIdx.x & 31;
    if (warp >= N_NODES) return;
    const float* ar = A + (size_t)warp * C2;
    float a0 = 0.0f, a1 = 0.0f;
#pragma unroll
    for (int k = lane; k < C2; k += 32) {
        float v = ar[k];
        a0 += v * W[k * 2 + 0];
        a1 += v * W[k * 2 + 1];
    }
#pragma unroll
    for (int o = 16; o > 0; o >>= 1) {
        a0 += __shfl_down_sync(0xffffffffu, a0, o);
        a1 += __shfl_down_sync(0xffffffffu, a1, o);
    }
    if (lane == 0) {
        out[(size_t)warp * 2 + 0] = a0;
        out[(size_t)warp * 2 + 1] = a1;
    }
}

__global__ void k_sigmoid_out(const float* __restrict__ a, const float* __restrict__ b,
                              float* __restrict__ out) {
    int i = blockIdx.x * blockDim.x + threadIdx.x;
    if (i < N_NODES * 2) {
        float v = a[i] + b[i & 1];
        out[i] = 1.0f / (1.0f + expf(-v));
    }
}

// ---------------- launch ----------------------------------------------------
extern "C" void kernel_launch(void* const* d_in, const int* in_sizes, int n_in,
                              void* d_out, int out_size) {
    const float* x  = (const float*)d_in[0];
    const int*   ei = (const int*)d_in[1];
    const float* W1 = (const float*)d_in[2];
    const float* b1 = (const float*)d_in[3];
    const float* W2 = (const float*)d_in[4];
    const float* b2 = (const float*)d_in[5];
    const float* W3 = (const float*)d_in[6];
    const float* b3 = (const float*)d_in[7];
    float* out = (float*)d_out;

    const int* src = ei;
    const int* dst = ei + N_EDGES;

    float* h1; cudaGetSymbolAddress((void**)&h1, g_h1);
    float* a1; cudaGetSymbolAddress((void**)&a1, g_a1);
    float* h2; cudaGetSymbolAddress((void**)&h2, g_h2);
    float* a2; cudaGetSymbolAddress((void**)&a2, g_a2);
    float* h3; cudaGetSymbolAddress((void**)&h3, g_h3);
    float* a3; cudaGetSymbolAddress((void**)&a3, g_a3);

    const int T = 256;

    // norm build
    k_deg_init<<<(N_NODES + T - 1) / T, T>>>();
    k_deg_acc<<<(N_EDGES + T - 1) / T, T>>>(dst);
    k_dinv<<<(N_NODES + T - 1) / T, T>>>();

    // ---- layer 1: h1 = x @ W1 ; a1 = A_norm h1 ; relu(a1 + b1)
    {
        dim3 grid(C1 / 128, (N_NODES + 127) / 128);
        tf32_gemm<<<grid, 256>>>(x, W1, h1, N_NODES, C_IN, C1);
    }
    k_self_init<C1><<<((size_t)N_NODES * (C1 / 4) + T - 1) / T, T>>>(h1, a1);
    k_edge_scatter<C1><<<((size_t)N_EDGES * 32 + T - 1) / T, T>>>(src, dst, h1, a1);
    k_bias_relu<C1><<<((size_t)N_NODES * (C1 / 4) + T - 1) / T, T>>>(a1, b1);

    // ---- layer 2
    {
        dim3 grid(C2 / 128, (N_NODES + 127) / 128);
        tf32_gemm<<<grid, 256>>>(a1, W2, h2, N_NODES, C1, C2);
    }
    k_self_init<C2><<<((size_t)N_NODES * (C2 / 4) + T - 1) / T, T>>>(h2, a2);
    k_edge_scatter<C2><<<((size_t)N_EDGES * 32 + T - 1) / T, T>>>(src, dst, h2, a2);
    k_bias_relu<C2><<<((size_t)N_NODES * (C2 / 4) + T - 1) / T, T>>>(a2, b2);

    // ---- layer 3: h3 = a2 @ W3 ; a3 = A_norm h3 ; sigmoid(a3 + b3)
    k_gemm3<<<((size_t)N_NODES * 32 + T - 1) / T, T>>>(a2, W3, h3);
    k_self_init2<<<(N_NODES + T - 1) / T, T>>>(h3, a3);
    k_edge_scatter2<<<(N_EDGES + T - 1) / T, T>>>(src, dst, h3, a3);
    k_sigmoid_out<<<(N_NODES * 2 + T - 1) / T, T>>>(a3, b3, out);
}

// round 4
// speedup vs baseline: 2.6944x; 1.2568x over previous
#include <cuda_runtime.h>
#include <math.h>

#define N_NODES 50000
#define N_EDGES 800000
#define C_IN    768
#define C1      256
#define C2      128
#define C3      2

#define SCAN_T  1024
#define SCAN_CH ((N_NODES + SCAN_T - 1) / SCAN_T)   // 49

// ---------------- scratch (device globals; no allocation allowed) ----------
__device__ float g_dinv[N_NODES];
__device__ int   g_cnt[N_NODES];
__device__ int   g_cnt2[N_NODES];
__device__ int   g_off[N_NODES + 1];
__device__ int   g_csr[N_EDGES];                 // src ids grouped by dst
__device__ float g_h1[(size_t)N_NODES * C1];
__device__ float g_a1[(size_t)N_NODES * C1];
__device__ float g_h2[(size_t)N_NODES * C2];
__device__ float g_a2[(size_t)N_NODES * C2];
__device__ float g_h3[(size_t)N_NODES * C3];

// ---------------- CSR build -------------------------------------------------
__global__ void k_zero_cnt() {
    int i = blockIdx.x * blockDim.x + threadIdx.x;
    if (i < N_NODES) { g_cnt[i] = 0; g_cnt2[i] = 0; }
}

__global__ void k_count(const int* __restrict__ dst) {
    int e = blockIdx.x * blockDim.x + threadIdx.x;
    if (e < N_EDGES) atomicAdd(&g_cnt[dst[e]], 1);
}

// single block, 1024 threads: exclusive scan of g_cnt -> g_off, plus dinv
__global__ void __launch_bounds__(SCAN_T) k_scan() {
    __shared__ int s_part[SCAN_T];
    const int t = threadIdx.x;
    const int start = t * SCAN_CH;
    const int end   = min(start + SCAN_CH, N_NODES);

    int sum = 0;
    for (int i = start; i < end; i++) {
        int c = g_cnt[i];
        sum += c;
        g_dinv[i] = rsqrtf((float)(c + 1));   // +1 self loop
    }
    s_part[t] = sum;
    __syncthreads();

    // inclusive Hillis-Steele scan
    for (int ofs = 1; ofs < SCAN_T; ofs <<= 1) {
        int v = 0;
        if (t >= ofs) v = s_part[t - ofs];
        __syncthreads();
        if (t >= ofs) s_part[t] += v;
        __syncthreads();
    }

    int run = (t == 0) ? 0 : s_part[t - 1];
    for (int i = start; i < end; i++) {
        g_off[i] = run;
        run += g_cnt[i];
    }
    if (start < N_NODES && end == N_NODES) g_off[N_NODES] = run;
}

__global__ void k_fill(const int* __restrict__ src, const int* __restrict__ dst) {
    int e = blockIdx.x * blockDim.x + threadIdx.x;
    if (e < N_EDGES) {
        int d = dst[e];
        int pos = g_off[d] + atomicAdd(&g_cnt2[d], 1);
        g_csr[pos] = src[e];
    }
}

// ---------------- TF32 tensor-core GEMM ------------------------------------
__device__ __forceinline__ float tf32r(float x) {
    unsigned u;
    asm("cvt.rna.tf32.f32 %0, %1;" : "=r"(u) : "f"(x));
    return __uint_as_float(u);
}

#define GLD 136   // padded row stride (words)

__global__ void __launch_bounds__(256) tf32_gemm(const float* __restrict__ A,
                                                 const float* __restrict__ B,
                                                 float* __restrict__ C,
                                                 int M, int K, int N) {
    __shared__ float As[2][16][GLD];   // [k][m]
    __shared__ float Bs[2][16][GLD];   // [k][n]

    const int tid  = threadIdx.x;
    const int warp = tid >> 5;
    const int lane = tid & 31;
    const int gid  = lane >> 2;
    const int tig  = lane & 3;
    const int wm   = warp & 1;
    const int wn   = warp >> 1;
    const int bm   = blockIdx.y * 128;
    const int bn   = blockIdx.x * 128;

    const int ar = tid >> 1;
    const int ak = (tid & 1) * 8;

    float acc[4][4][4];
#pragma unroll
    for (int i = 0; i < 4; i++)
#pragma unroll
        for (int j = 0; j < 4; j++)
#pragma unroll
            for (int q = 0; q < 4; q++) acc[i][j][q] = 0.0f;

    float4 la0, la1, lb0, lb1;

    {
        int gr = bm + ar;
        if (gr < M) {
            la0 = *(const float4*)(A + (size_t)gr * K + ak);
            la1 = *(const float4*)(A + (size_t)gr * K + ak + 4);
        } else {
            la0 = make_float4(0.f, 0.f, 0.f, 0.f); la1 = la0;
        }
#pragma unroll
        for (int i = 0; i < 2; i++) {
            int f = tid + i * 256;
            int r = f >> 5, c4 = f & 31;
            float4 v = *(const float4*)(B + (size_t)r * N + bn + c4 * 4);
            if (i == 0) lb0 = v; else lb1 = v;
        }
        As[0][ak + 0][ar] = tf32r(la0.x); As[0][ak + 1][ar] = tf32r(la0.y);
        As[0][ak + 2][ar] = tf32r(la0.z); As[0][ak + 3][ar] = tf32r(la0.w);
        As[0][ak + 4][ar] = tf32r(la1.x); As[0][ak + 5][ar] = tf32r(la1.y);
        As[0][ak + 6][ar] = tf32r(la1.z); As[0][ak + 7][ar] = tf32r(la1.w);
#pragma unroll
        for (int i = 0; i < 2; i++) {
            int f = tid + i * 256;
            int r = f >> 5, c4 = f & 31;
            float4 v = (i == 0) ? lb0 : lb1;
            Bs[0][r][c4 * 4 + 0] = tf32r(v.x);
            Bs[0][r][c4 * 4 + 1] = tf32r(v.y);
            Bs[0][r][c4 * 4 + 2] = tf32r(v.z);
            Bs[0][r][c4 * 4 + 3] = tf32r(v.w);
        }
    }
    __syncthreads();

    const int nIter = K / 16;
    for (int it = 0; it < nIter; it++) {
        int buf = it & 1;
        bool hasNext = (it + 1) < nIter;

        if (hasNext) {
            int k0 = (it + 1) * 16;
            int gr = bm + ar;
            if (gr < M) {
                la0 = *(const float4*)(A + (size_t)gr * K + k0 + ak);
                la1 = *(const float4*)(A + (size_t)gr * K + k0 + ak + 4);
            } else {
                la0 = make_float4(0.f, 0.f, 0.f, 0.f); la1 = la0;
            }
            {
                int f = tid;
                int r = f >> 5, c4 = f & 31;
                lb0 = *(const float4*)(B + (size_t)(k0 + r) * N + bn + c4 * 4);
                f = tid + 256; r = f >> 5; c4 = f & 31;
                lb1 = *(const float4*)(B + (size_t)(k0 + r) * N + bn + c4 * 4);
            }
        }

#pragma unroll
        for (int ks = 0; ks < 2; ks++) {
            int kk = ks * 8;
            unsigned af[4][4], bf[4][2];
#pragma unroll
            for (int im = 0; im < 4; im++) {
                int m = wm * 64 + im * 16 + gid;
                af[im][0] = __float_as_uint(As[buf][kk + tig][m]);
                af[im][1] = __float_as_uint(As[buf][kk + tig][m + 8]);
                af[im][2] = __float_as_uint(As[buf][kk + tig + 4][m]);
                af[im][3] = __float_as_uint(As[buf][kk + tig + 4][m + 8]);
            }
#pragma unroll
            for (int in_ = 0; in_ < 4; in_++) {
                int n = wn * 32 + in_ * 8 + gid;
                bf[in_][0] = __float_as_uint(Bs[buf][kk + tig][n]);
                bf[in_][1] = __float_as_uint(Bs[buf][kk + tig + 4][n]);
            }
#pragma unroll
            for (int im = 0; im < 4; im++)
#pragma unroll
                for (int in_ = 0; in_ < 4; in_++) {
                    asm volatile(
                        "mma.sync.aligned.m16n8k8.row.col.f32.tf32.tf32.f32 "
                        "{%0,%1,%2,%3}, {%4,%5,%6,%7}, {%8,%9}, {%0,%1,%2,%3};"
                        : "+f"(acc[im][in_][0]), "+f"(acc[im][in_][1]),
                          "+f"(acc[im][in_][2]), "+f"(acc[im][in_][3])
                        : "r"(af[im][0]), "r"(af[im][1]),
                          "r"(af[im][2]), "r"(af[im][3]),
                          "r"(bf[in_][0]), "r"(bf[in_][1]));
                }
        }

        if (hasNext) {
            int nb = buf ^ 1;
            As[nb][ak + 0][ar] = tf32r(la0.x); As[nb][ak + 1][ar] = tf32r(la0.y);
            As[nb][ak + 2][ar] = tf32r(la0.z); As[nb][ak + 3][ar] = tf32r(la0.w);
            As[nb][ak + 4][ar] = tf32r(la1.x); As[nb][ak + 5][ar] = tf32r(la1.y);
            As[nb][ak + 6][ar] = tf32r(la1.z); As[nb][ak + 7][ar] = tf32r(la1.w);
            {
                int f = tid;
                int r = f >> 5, c4 = f & 31;
                Bs[nb][r][c4 * 4 + 0] = tf32r(lb0.x);
                Bs[nb][r][c4 * 4 + 1] = tf32r(lb0.y);
                Bs[nb][r][c4 * 4 + 2] = tf32r(lb0.z);
                Bs[nb][r][c4 * 4 + 3] = tf32r(lb0.w);
                f = tid + 256; r = f >> 5; c4 = f & 31;
                Bs[nb][r][c4 * 4 + 0] = tf32r(lb1.x);
                Bs[nb][r][c4 * 4 + 1] = tf32r(lb1.y);
                Bs[nb][r][c4 * 4 + 2] = tf32r(lb1.z);
                Bs[nb][r][c4 * 4 + 3] = tf32r(lb1.w);
            }
            __syncthreads();
        }
    }

#pragma unroll
    for (int im = 0; im < 4; im++) {
        int r0 = bm + wm * 64 + im * 16 + gid;
        int r1 = r0 + 8;
#pragma unroll
        for (int in_ = 0; in_ < 4; in_++) {
            int c = bn + wn * 32 + in_ * 8 + 2 * tig;
            if (r0 < M) {
                float2 v = make_float2(acc[im][in_][0], acc[im][in_][1]);
                *(float2*)(C + (size_t)r0 * N + c) = v;
            }
            if (r1 < M) {
                float2 v = make_float2(acc[im][in_][2], acc[im][in_][3]);
                *(float2*)(C + (size_t)r1 * N + c) = v;
            }
        }
    }
}

// ---------------- CSR gather aggregation ------------------------------------
// warp per node; lane owns VEC float4 channel chunks (channel-major coalesced).
// out[d,:] = relu( (sum_{s in N(d)} dinv[s]*h[s,:] + dinv[d]*h[d,:]) * dinv[d] + b )
template <int C, bool RELU>
__global__ void __launch_bounds__(256) k_gather(const float* __restrict__ h,
                                                const float* __restrict__ bias,
                                                float* __restrict__ out) {
    constexpr int VEC = C / 128;            // float4 chunks per lane
    const int warpId = (blockIdx.x * blockDim.x + threadIdx.x) >> 5;
    const int lane = threadIdx.x & 31;
    if (warpId >= N_NODES) return;
    const int node = warpId;

    float4 acc[VEC];
#pragma unroll
    for (int v = 0; v < VEC; v++) acc[v] = make_float4(0.f, 0.f, 0.f, 0.f);

    const int e0 = g_off[node];
    const int e1 = g_off[node + 1];
    for (int e = e0; e < e1; e++) {
        int s = g_csr[e];
        float w = g_dinv[s];
        const float4* hs = (const float4*)(h + (size_t)s * C);
#pragma unroll
        for (int v = 0; v < VEC; v++) {
            float4 f = hs[lane + v * 32];
            acc[v].x += f.x * w; acc[v].y += f.y * w;
            acc[v].z += f.z * w; acc[v].w += f.w * w;
        }
    }

    float dd = g_dinv[node];
    const float4* hn = (const float4*)(h + (size_t)node * C);
    float4* on = (float4*)(out + (size_t)node * C);
#pragma unroll
    for (int v = 0; v < VEC; v++) {
        float4 f = hn[lane + v * 32];
        float4 b = ((const float4*)bias)[lane + v * 32];
        float4 r;
        r.x = (acc[v].x + f.x * dd) * dd + b.x;
        r.y = (acc[v].y + f.y * dd) * dd + b.y;
        r.z = (acc[v].z + f.z * dd) * dd + b.z;
        r.w = (acc[v].w + f.w * dd) * dd + b.w;
        if (RELU) {
            r.x = fmaxf(r.x, 0.f); r.y = fmaxf(r.y, 0.f);
            r.z = fmaxf(r.z, 0.f); r.w = fmaxf(r.w, 0.f);
        }
        on[lane + v * 32] = r;
    }
}

// layer-3 gather (C=2): warp per node, lanes stride edges, fused sigmoid
__global__ void __launch_bounds__(256) k_gather2_sig(const float* __restrict__ h,
                                                     const float* __restrict__ bias,
                                                     float* __restrict__ out) {
    const int warpId = (blockIdx.x * blockDim.x + threadIdx.x) >> 5;
    const int lane = threadIdx.x & 31;
    if (warpId >= N_NODES) return;
    const int node = warpId;

    float a0 = 0.f, a1 = 0.f;
    const int e0 = g_off[node];
    const int e1 = g_off[node + 1];
    for (int e = e0 + lane; e < e1; e += 32) {
        int s = g_csr[e];
        float w = g_dinv[s];
        float2 f = ((const float2*)h)[s];
        a0 += f.x * w;
        a1 += f.y * w;
    }
#pragma unroll
    for (int o = 16; o > 0; o >>= 1) {
        a0 += __shfl_down_sync(0xffffffffu, a0, o);
        a1 += __shfl_down_sync(0xffffffffu, a1, o);
    }
    if (lane == 0) {
        float dd = g_dinv[node];
        float2 f = ((const float2*)h)[node];
        float r0 = (a0 + f.x * dd) * dd + bias[0];
        float r1 = (a1 + f.y * dd) * dd + bias[1];
        float2 o2;
        o2.x = 1.0f / (1.0f + expf(-r0));
        o2.y = 1.0f / (1.0f + expf(-r1));
        ((float2*)out)[node] = o2;
    }
}

// ---------------- layer-3 GEMM (K=128 -> 2 outputs), warp per row ----------
__global__ void k_gemm3(const float* __restrict__ A, const float* __restrict__ W,
                        float* __restrict__ out) {
    int warp = (blockIdx.x * blockDim.x + threadIdx.x) >> 5;
    int lane = threadIdx.x & 31;
    if (warp >= N_NODES) return;
    const float* ar = A + (size_t)warp * C2;
    float a0 = 0.0f, a1 = 0.0f;
#pragma unroll
    for (int k = lane; k < C2; k += 32) {
        float v = ar[k];
        a0 += v * W[k * 2 + 0];
        a1 += v * W[k * 2 + 1];
    }
#pragma unroll
    for (int o = 16; o > 0; o >>= 1) {
        a0 += __shfl_down_sync(0xffffffffu, a0, o);
        a1 += __shfl_down_sync(0xffffffffu, a1, o);
    }
    if (lane == 0) {
        out[(size_t)warp * 2 + 0] = a0;
        out[(size_t)warp * 2 + 1] = a1;
    }
}

// ---------------- launch ----------------------------------------------------
extern "C" void kernel_launch(void* const* d_in, const int* in_sizes, int n_in,
                              void* d_out, int out_size) {
    const float* x  = (const float*)d_in[0];
    const int*   ei = (const int*)d_in[1];
    const float* W1 = (const float*)d_in[2];
    const float* b1 = (const float*)d_in[3];
    const float* W2 = (const float*)d_in[4];
    const float* b2 = (const float*)d_in[5];
    const float* W3 = (const float*)d_in[6];
    const float* b3 = (const float*)d_in[7];
    float* out = (float*)d_out;

    const int* src = ei;
    const int* dst = ei + N_EDGES;

    float* h1; cudaGetSymbolAddress((void**)&h1, g_h1);
    float* a1; cudaGetSymbolAddress((void**)&a1, g_a1);
    float* h2; cudaGetSymbolAddress((void**)&h2, g_h2);
    float* a2; cudaGetSymbolAddress((void**)&a2, g_a2);
    float* h3; cudaGetSymbolAddress((void**)&h3, g_h3);

    const int T = 256;

    // ---- CSR build (every call; deterministic)
    k_zero_cnt<<<(N_NODES + T - 1) / T, T>>>();
    k_count<<<(N_EDGES + T - 1) / T, T>>>(dst);
    k_scan<<<1, SCAN_T>>>();
    k_fill<<<(N_EDGES + T - 1) / T, T>>>(src, dst);

    // ---- layer 1
    {
        dim3 grid(C1 / 128, (N_NODES + 127) / 128);
        tf32_gemm<<<grid, 256>>>(x, W1, h1, N_NODES, C_IN, C1);
    }
    k_gather<C1, true><<<(N_NODES * 32 + T - 1) / T, T>>>(h1, b1, a1);

    // ---- layer 2
    {
        dim3 grid(C2 / 128, (N_NODES + 127) / 128);
        tf32_gemm<<<grid, 256>>>(a1, W2, h2, N_NODES, C1, C2);
    }
    k_gather<C2, true><<<(N_NODES * 32 + T - 1) / T, T>>>(h2, b2, a2);

    // ---- layer 3
    k_gemm3<<<(N_NODES * 32 + T - 1) / T, T>>>(a2, W3, h3);
    k_gather2_sig<<<(N_NODES * 32 + T - 1) / T, T>>>(h3, b3, out);
}

// round 8
// speedup vs baseline: 3.2840x; 1.2188x over previous
#include <cuda_runtime.h>
#include <cuda_bf16.h>
#include <stdint.h>
#include <math.h>

#define N_NODES 50000
#define N_EDGES 800000
#define C_IN    768
#define C1      256
#define C2      128
#define C3      2

#define SCAN_T  1024
#define SCAN_CH ((N_NODES + SCAN_T - 1) / SCAN_T)   // 49

// ---------------- scratch (device globals; no allocation allowed) ----------
__device__ float g_dinv[N_NODES];
__device__ int   g_cnt[N_NODES];
__device__ int   g_cnt2[N_NODES];
__device__ int   g_off[N_NODES + 1];
__device__ int   g_csr[N_EDGES];                        // src ids grouped by dst
__device__ __nv_bfloat16 g_h1[(size_t)N_NODES * C1];    // x@W1 (bf16)
__device__ float g_a1[(size_t)N_NODES * C1];
__device__ __nv_bfloat16 g_h2[(size_t)N_NODES * C2];    // a1@W2 (bf16)
__device__ float g_a2[(size_t)N_NODES * C2];
__device__ float g_h3[(size_t)N_NODES * C3];

// ---------------- CSR build -------------------------------------------------
__global__ void k_zero_cnt() {
    int i = blockIdx.x * blockDim.x + threadIdx.x;
    if (i < N_NODES) { g_cnt[i] = 0; g_cnt2[i] = 0; }
}

__global__ void k_count(const int* __restrict__ dst) {
    int e = blockIdx.x * blockDim.x + threadIdx.x;
    if (e < N_EDGES) atomicAdd(&g_cnt[dst[e]], 1);
}

__global__ void __launch_bounds__(SCAN_T) k_scan() {
    __shared__ int s_part[SCAN_T];
    const int t = threadIdx.x;
    const int start = t * SCAN_CH;
    const int end   = min(start + SCAN_CH, N_NODES);

    int sum = 0;
    for (int i = start; i < end; i++) {
        int c = g_cnt[i];
        sum += c;
        g_dinv[i] = rsqrtf((float)(c + 1));   // +1 self loop
    }
    s_part[t] = sum;
    __syncthreads();
    for (int ofs = 1; ofs < SCAN_T; ofs <<= 1) {
        int v = 0;
        if (t >= ofs) v = s_part[t - ofs];
        __syncthreads();
        if (t >= ofs) s_part[t] += v;
        __syncthreads();
    }
    int run = (t == 0) ? 0 : s_part[t - 1];
    for (int i = start; i < end; i++) {
        g_off[i] = run;
        run += g_cnt[i];
    }
    if (start < N_NODES && end == N_NODES) g_off[N_NODES] = run;
}

__global__ void k_fill(const int* __restrict__ src, const int* __restrict__ dst) {
    int e = blockIdx.x * blockDim.x + threadIdx.x;
    if (e < N_EDGES) {
        int d = dst[e];
        int pos = g_off[d] + atomicAdd(&g_cnt2[d], 1);
        g_csr[pos] = src[e];
    }
}

// ---------------- TF32 tensor-core GEMM, 3-stage cp.async -------------------
// C[M,N] = A[M,K] @ B[K,N]. BM=BN=128, BK=16, 256 thr, warp tile 64x32.
// As[m][AST] (m-major), Bs[k][BST]. tf32 via bit truncation (no cvt).
#define AST 20
#define BST 136
#define AS_WORDS (128 * AST)   // 2560
#define BS_WORDS (16 * BST)    // 2176
#define GEMM_SMEM ((3 * AS_WORDS + 3 * BS_WORDS) * 4)   // 56832 B

__device__ __forceinline__ void cp16(unsigned int dst, const void* src, bool pred) {
    asm volatile("cp.async.cg.shared.global [%0], [%1], 16, %2;"
                 :: "r"(dst), "l"(src), "r"(pred ? 16 : 0));
}

template <bool OUT_BF16>
__global__ void __launch_bounds__(256) tf32_gemm(const float* __restrict__ A,
                                                 const float* __restrict__ B,
                                                 void* __restrict__ Cout,
                                                 int M, int K, int N) {
    extern __shared__ float sm[];
    const int tid  = threadIdx.x;
    const int warp = tid >> 5;
    const int lane = tid & 31;
    const int gid  = lane >> 2;
    const int tig  = lane & 3;
    const int wm   = warp & 1;
    const int wn   = warp >> 1;
    const int bm   = blockIdx.y * 128;
    const int bn   = blockIdx.x * 128;

    unsigned int sbase;
    asm("{ .reg .u64 t; cvta.to.shared.u64 t, %1; cvt.u32.u64 %0, t; }"
        : "=r"(sbase) : "l"(sm));

    float acc[4][4][4];
#pragma unroll
    for (int i = 0; i < 4; i++)
#pragma unroll
        for (int j = 0; j < 4; j++)
#pragma unroll
            for (int q = 0; q < 4; q++) acc[i][j][q] = 0.0f;

    const int nIter = K / 16;

    // stage issue: A tile 512 x 16B chunks, B tile 512 x 16B chunks
    auto issue = [&](int stage, int k0) {
        unsigned int aB = sbase + (unsigned int)stage * AS_WORDS * 4;
        unsigned int bB = sbase + (unsigned int)(3 * AS_WORDS + stage * BS_WORDS) * 4;
        {
            int c = tid, r = c >> 2, kc = c & 3;
            cp16(aB + (unsigned int)(r * AST + kc * 4) * 4,
                 A + (size_t)(bm + r) * K + k0 + kc * 4, (bm + r) < M);
        }
        {
            int c = tid + 256, r = c >> 2, kc = c & 3;
            cp16(aB + (unsigned int)(r * AST + kc * 4) * 4,
                 A + (size_t)(bm + r) * K + k0 + kc * 4, (bm + r) < M);
        }
        {
            int c = tid, r = c >> 5, n4 = c & 31;
            cp16(bB + (unsigned int)(r * BST + n4 * 4) * 4,
                 B + (size_t)(k0 + r) * N + bn + n4 * 4, true);
        }
        {
            int c = tid + 256, r = c >> 5, n4 = c & 31;
            cp16(bB + (unsigned int)(r * BST + n4 * 4) * 4,
                 B + (size_t)(k0 + r) * N + bn + n4 * 4, true);
        }
        asm volatile("cp.async.commit_group;");
    };

    issue(0, 0);
    issue(1, 16);

    for (int it = 0; it < nIter; it++) {
        asm volatile("cp.async.wait_group 1;");
        __syncthreads();

        if (it + 2 < nIter) issue((it + 2) % 3, (it + 2) * 16);

        const int stage = it % 3;
        const float* Asb = sm + stage * AS_WORDS;
        const float* Bsb = sm + 3 * AS_WORDS + stage * BS_WORDS;

#pragma unroll
        for (int ks = 0; ks < 2; ks++) {
            int kk = ks * 8;
            unsigned af[4][4], bf[4][2];
#pragma unroll
            for (int im = 0; im < 4; im++) {
                int m = wm * 64 + im * 16 + gid;
                af[im][0] = __float_as_uint(Asb[m * AST + kk + tig]);
                af[im][1] = __float_as_uint(Asb[(m + 8) * AST + kk + tig]);
                af[im][2] = __float_as_uint(Asb[m * AST + kk + tig + 4]);
                af[im][3] = __float_as_uint(Asb[(m + 8) * AST + kk + tig + 4]);
            }
#pragma unroll
            for (int in_ = 0; in_ < 4; in_++) {
                int n = wn * 32 + in_ * 8 + gid;
                bf[in_][0] = __float_as_uint(Bsb[(kk + tig) * BST + n]);
                bf[in_][1] = __float_as_uint(Bsb[(kk + tig + 4) * BST + n]);
            }
#pragma unroll
            for (int im = 0; im < 4; im++)
#pragma unroll
                for (int in_ = 0; in_ < 4; in_++) {
                    asm volatile(
                        "mma.sync.aligned.m16n8k8.row.col.f32.tf32.tf32.f32 "
                        "{%0,%1,%2,%3}, {%4,%5,%6,%7}, {%8,%9}, {%0,%1,%2,%3};"
                        : "+f"(acc[im][in_][0]), "+f"(acc[im][in_][1]),
                          "+f"(acc[im][in_][2]), "+f"(acc[im][in_][3])
                        : "r"(af[im][0]), "r"(af[im][1]),
                          "r"(af[im][2]), "r"(af[im][3]),
                          "r"(bf[in_][0]), "r"(bf[in_][1]));
                }
        }
    }

    // ---- epilogue
#pragma unroll
    for (int im = 0; im < 4; im++) {
        int r0 = bm + wm * 64 + im * 16 + gid;
        int r1 = r0 + 8;
#pragma unroll
        for (int in_ = 0; in_ < 4; in_++) {
            int c = bn + wn * 32 + in_ * 8 + 2 * tig;
            if (OUT_BF16) {
                __nv_bfloat16* ob = (__nv_bfloat16*)Cout;
                if (r0 < M)
                    *(__nv_bfloat162*)(ob + (size_t)r0 * N + c) =
                        __floats2bfloat162_rn(acc[im][in_][0], acc[im][in_][1]);
                if (r1 < M)
                    *(__nv_bfloat162*)(ob + (size_t)r1 * N + c) =
                        __floats2bfloat162_rn(acc[im][in_][2], acc[im][in_][3]);
            } else {
                float* of = (float*)Cout;
                if (r0 < M)
                    *(float2*)(of + (size_t)r0 * N + c) =
                        make_float2(acc[im][in_][0], acc[im][in_][1]);
                if (r1 < M)
                    *(float2*)(of + (size_t)r1 * N + c) =
                        make_float2(acc[im][in_][2], acc[im][in_][3]);
            }
        }
    }
}

// ---------------- CSR gather aggregation (bf16 in, fp32 out) ----------------
// warp per node. C=256: lane owns 8 channels (uint4 = 8 bf16).
__global__ void __launch_bounds__(256) k_gather256(const __nv_bfloat16* __restrict__ h,
                                                   const float* __restrict__ bias,
                                                   float* __restrict__ out) {
    const int node = (blockIdx.x * blockDim.x + threadIdx.x) >> 5;
    const int lane = threadIdx.x & 31;
    if (node >= N_NODES) return;

    float acc[8];
#pragma unroll
    for (int i = 0; i < 8; i++) acc[i] = 0.f;

    const int e0 = g_off[node];
    const int e1 = g_off[node + 1];
    for (int e = e0; e < e1; e++) {
        int s = g_csr[e];
        float w = g_dinv[s];
        uint4 q = ((const uint4*)(h + (size_t)s * C1))[lane];
        float2 f0 = __bfloat1622float2(*(__nv_bfloat162*)&q.x);
        float2 f1 = __bfloat1622float2(*(__nv_bfloat162*)&q.y);
        float2 f2 = __bfloat1622float2(*(__nv_bfloat162*)&q.z);
        float2 f3 = __bfloat1622float2(*(__nv_bfloat162*)&q.w);
        acc[0] += f0.x * w; acc[1] += f0.y * w;
        acc[2] += f1.x * w; acc[3] += f1.y * w;
        acc[4] += f2.x * w; acc[5] += f2.y * w;
        acc[6] += f3.x * w; acc[7] += f3.y * w;
    }

    float dd = g_dinv[node];
    uint4 q = ((const uint4*)(h + (size_t)node * C1))[lane];
    float2 f0 = __bfloat1622float2(*(__nv_bfloat162*)&q.x);
    float2 f1 = __bfloat1622float2(*(__nv_bfloat162*)&q.y);
    float2 f2 = __bfloat1622float2(*(__nv_bfloat162*)&q.z);
    float2 f3 = __bfloat1622float2(*(__nv_bfloat162*)&q.w);
    float sf[8] = {f0.x, f0.y, f1.x, f1.y, f2.x, f2.y, f3.x, f3.y};

    float4 b0 = ((const float4*)bias)[lane * 2 + 0];
    float4 b1 = ((const float4*)bias)[lane * 2 + 1];
    float bb[8] = {b0.x, b0.y, b0.z, b0.w, b1.x, b1.y, b1.z, b1.w};

    float r[8];
#pragma unroll
    for (int i = 0; i < 8; i++)
        r[i] = fmaxf((acc[i] + sf[i] * dd) * dd + bb[i], 0.f);

    float4* on = (float4*)(out + (size_t)node * C1 + lane * 8);
    on[0] = make_float4(r[0], r[1], r[2], r[3]);
    on[1] = make_float4(r[4], r[5], r[6], r[7]);
}

// C=128: lane owns 4 channels (uint2 = 4 bf16).
__global__ void __launch_bounds__(256) k_gather128(const __nv_bfloat16* __restrict__ h,
                                                   const float* __restrict__ bias,
                                                   float* __restrict__ out) {
    const int node = (blockIdx.x * blockDim.x + threadIdx.x) >> 5;
    const int lane = threadIdx.x & 31;
    if (node >= N_NODES) return;

    float acc[4] = {0.f, 0.f, 0.f, 0.f};

    const int e0 = g_off[node];
    const int e1 = g_off[node + 1];
    for (int e = e0; e < e1; e++) {
        int s = g_csr[e];
        float w = g_dinv[s];
        uint2 q = ((const uint2*)(h + (size_t)s * C2))[lane];
        float2 f0 = __bfloat1622float2(*(__nv_bfloat162*)&q.x);
        float2 f1 = __bfloat1622float2(*(__nv_bfloat162*)&q.y);
        acc[0] += f0.x * w; acc[1] += f0.y * w;
        acc[2] += f1.x * w; acc[3] += f1.y * w;
    }

    float dd = g_dinv[node];
    uint2 q = ((const uint2*)(h + (size_t)node * C2))[lane];
    float2 f0 = __bfloat1622float2(*(__nv_bfloat162*)&q.x);
    float2 f1 = __bfloat1622float2(*(__nv_bfloat162*)&q.y);
    float sf[4] = {f0.x, f0.y, f1.x, f1.y};

    float4 b = ((const float4*)bias)[lane];
    float bb[4] = {b.x, b.y, b.z, b.w};

    float r[4];
#pragma unroll
    for (int i = 0; i < 4; i++)
        r[i] = fmaxf((acc[i] + sf[i] * dd) * dd + bb[i], 0.f);

    *(float4*)(out + (size_t)node * C2 + lane * 4) = make_float4(r[0], r[1], r[2], r[3]);
}

// layer-3 gather (C=2): warp per node, lanes stride edges, fused sigmoid
__global__ void __launch_bounds__(256) k_gather2_sig(const float* __restrict__ h,
                                                     const float* __restrict__ bias,
                                                     float* __restrict__ out) {
    const int node = (blockIdx.x * blockDim.x + threadIdx.x) >> 5;
    const int lane = threadIdx.x & 31;
    if (node >= N_NODES) return;

    float a0 = 0.f, a1 = 0.f;
    const int e0 = g_off[node];
    const int e1 = g_off[node + 1];
    for (int e = e0 + lane; e < e1; e += 32) {
        int s = g_csr[e];
        float w = g_dinv[s];
        float2 f = ((const float2*)h)[s];
        a0 += f.x * w;
        a1 += f.y * w;
    }
#pragma unroll
    for (int o = 16; o > 0; o >>= 1) {
        a0 += __shfl_down_sync(0xffffffffu, a0, o);
        a1 += __shfl_down_sync(0xffffffffu, a1, o);
    }
    if (lane == 0) {
        float dd = g_dinv[node];
        float2 f = ((const float2*)h)[node];
        float r0 = (a0 + f.x * dd) * dd + bias[0];
        float r1 = (a1 + f.y * dd) * dd + bias[1];
        float2 o2;
        o2.x = 1.0f / (1.0f + expf(-r0));
        o2.y = 1.0f / (1.0f + expf(-r1));
        ((float2*)out)[node] = o2;
    }
}

// ---------------- layer-3 GEMM (K=128 -> 2 outputs), warp per row ----------
__global__ void k_gemm3(const float* __restrict__ A, const float* __restrict__ W,
                        float* __restrict__ out) {
    int warp = (blockIdx.x * blockDim.x + threadIdx.x) >> 5;
    int lane = threadIdx.x & 31;
    if (warp >= N_NODES) return;
    const float* ar = A + (size_t)warp * C2;
    float a0 = 0.0f, a1 = 0.0f;
#pragma unroll
    for (int k = lane; k < C2; k += 32) {
        float v = ar[k];
        a0 += v * W[k * 2 + 0];
        a1 += v * W[k * 2 + 1];
    }
#pragma unroll
    for (int o = 16; o > 0; o >>= 1) {
        a0 += __shfl_down_sync(0xffffffffu, a0, o);
        a1 += __shfl_down_sync(0xffffffffu, a1, o);
    }
    if (lane == 0) {
        out[(size_t)warp * 2 + 0] = a0;
        out[(size_t)warp * 2 + 1] = a1;
    }
}

// ---------------- launch ----------------------------------------------------
extern "C" void kernel_launch(void* const* d_in, const int* in_sizes, int n_in,
                              void* d_out, int out_size) {
    const float* x  = (const float*)d_in[0];
    const int*   ei = (const int*)d_in[1];
    const float* W1 = (const float*)d_in[2];
    const float* b1 = (const float*)d_in[3];
    const float* W2 = (const float*)d_in[4];
    const float* b2 = (const float*)d_in[5];
    const float* W3 = (const float*)d_in[6];
    const float* b3 = (const float*)d_in[7];
    float* out = (float*)d_out;

    const int* src = ei;
    const int* dst = ei + N_EDGES;

    __nv_bfloat16* h1; cudaGetSymbolAddress((void**)&h1, g_h1);
    float* a1;         cudaGetSymbolAddress((void**)&a1, g_a1);
    __nv_bfloat16* h2; cudaGetSymbolAddress((void**)&h2, g_h2);
    float* a2;         cudaGetSymbolAddress((void**)&a2, g_a2);
    float* h3;         cudaGetSymbolAddress((void**)&h3, g_h3);

    cudaFuncSetAttribute(tf32_gemm<true>,
                         cudaFuncAttributeMaxDynamicSharedMemorySize, GEMM_SMEM);

    const int T = 256;

    // ---- CSR build (every call; deterministic)
    k_zero_cnt<<<(N_NODES + T - 1) / T, T>>>();
    k_count<<<(N_EDGES + T - 1) / T, T>>>(dst);
    k_scan<<<1, SCAN_T>>>();
    k_fill<<<(N_EDGES + T - 1) / T, T>>>(src, dst);

    // ---- layer 1
    {
        dim3 grid(C1 / 128, (N_NODES + 127) / 128);
        tf32_gemm<true><<<grid, 256, GEMM_SMEM>>>(x, W1, h1, N_NODES, C_IN, C1);
    }
    k_gather256<<<(N_NODES * 32 + T - 1) / T, T>>>(h1, b1, a1);

    // ---- layer 2
    {
        dim3 grid(C2 / 128, (N_NODES + 127) / 128);
        tf32_gemm<true><<<grid, 256, GEMM_SMEM>>>(a1, W2, h2, N_NODES, C1, C2);
    }
    k_gather128<<<(N_NODES * 32 + T - 1) / T, T>>>(h2, b2, a2);

    // ---- layer 3
    k_gemm3<<<(N_NODES * 32 + T - 1) / T, T>>>(a2, W3, h3);
    k_gather2_sig<<<(N_NODES * 32 + T - 1) / T, T>>>(h3, b3, out);
}